// round 3
// baseline (speedup 1.0000x reference)
#include <cuda_runtime.h>
#include <math_constants.h>

// Problem constants
#define NE     8192     // num codebook entries
#define ED     256      // embedding dim
#define NROWS  16384    // 16*32*32 flattened vectors
#define OUT_ZQ 4194304  // 16*32*32*256 elements of z_q_st
// out layout: [0, OUT_ZQ) = z_q_st, [OUT_ZQ] = loss, [OUT_ZQ+1, +NROWS) = indices

#define KTILES 64       // 8192 / 128
#define MTILES 128      // 16384 / 128

// ---- scratch (static device globals; no allocation allowed) ----
__device__ float  g_z2[NROWS];
__device__ float  g_e2[NE];
__device__ float  g_bestD[KTILES][NROWS];
__device__ int    g_bestI[KTILES][NROWS];
__device__ int    g_eidx[NROWS];
__device__ double g_losspart[16384];

// ---------------------------------------------------------------
// z2[n] = sum_c z[b][c][h][w]^2 ; n = b*1024 + h*32 + w
// consecutive n -> consecutive gmem addresses for fixed c (coalesced)
// ---------------------------------------------------------------
__global__ void k_z2(const float* __restrict__ z) {
    int n = blockIdx.x * blockDim.x + threadIdx.x;
    if (n >= NROWS) return;
    int b  = n >> 10;
    int hw = n & 1023;
    const float* p = z + (size_t)b * (ED * 1024) + hw;
    float s = 0.0f;
#pragma unroll 8
    for (int c = 0; c < ED; ++c) {
        float v = p[c * 1024];
        s = fmaf(v, v, s);
    }
    g_z2[n] = s;
}

// ---------------------------------------------------------------
// e2[k] = sum_c codebook[k][c]^2  (warp per code)
// ---------------------------------------------------------------
__global__ void k_e2(const float* __restrict__ cb) {
    int code = blockIdx.x * (blockDim.x >> 5) + (threadIdx.x >> 5);
    int lane = threadIdx.x & 31;
    if (code >= NE) return;
    const float* r = cb + (size_t)code * ED;
    float s = 0.0f;
#pragma unroll
    for (int i = lane; i < ED; i += 32) {
        float v = r[i];
        s = fmaf(v, v, s);
    }
#pragma unroll
    for (int o = 16; o; o >>= 1) s += __shfl_xor_sync(0xffffffffu, s, o);
    if (lane == 0) g_e2[code] = s;
}

// ---------------------------------------------------------------
// Main: per (mtile, ktile) block: 128 rows x 128 codes, full C=256
// dot, then quantized-distance argmin partial per row.
// BM=BN=128, BK=16, 256 threads, 8x8 per thread, smem double buffer.
// ---------------------------------------------------------------
#define BM 128
#define BN 128
#define BK 16

__global__ __launch_bounds__(256, 2)
void k_argmin(const float* __restrict__ z, const float* __restrict__ cb) {
    const int ktile = blockIdx.x;   // 0..63
    const int mtile = blockIdx.y;   // 0..127

    __shared__ float As[2][BK][BM];
    __shared__ float Bs[2][BK][BN];
    __shared__ float z2s[BM];
    __shared__ float e2s[BN];

    const int tid = threadIdx.x;
    const int tx  = tid & 15;
    const int ty  = tid >> 4;

    const int row0 = mtile * BM;
    const int col0 = ktile * BN;

    // A(r,c) = z[b][c][hw0+r] ; all 128 rows share b since 128 | 1024
    const int b   = row0 >> 10;
    const int hw0 = row0 & 1023;
    const float* Ab = z  + (size_t)b    * (ED * 1024) + hw0;
    const float* Bb = cb + (size_t)col0 * ED;

    if (tid < BM) z2s[tid] = g_z2[row0 + tid];
    else          e2s[tid - BM] = g_e2[col0 + (tid - BM)];

    float acc[8][8];
#pragma unroll
    for (int i = 0; i < 8; ++i)
#pragma unroll
        for (int j = 0; j < 8; ++j) acc[i][j] = 0.0f;

    float4 ar[2], br[2];

    // ---- stage-0 loads ----
    {
        const int cbase = 0;
#pragma unroll
        for (int q = 0; q < 2; ++q) {
            int fid = tid + q * 256;          // 0..511
            int c   = fid >> 5;               // 0..15
            int r4  = (fid & 31) * 4;         // 0..124
            ar[q] = *reinterpret_cast<const float4*>(Ab + (size_t)(cbase + c) * 1024 + r4);
            int code = fid >> 2;              // 0..127
            int cp4  = (fid & 3) * 4;         // 0,4,8,12
            br[q] = *reinterpret_cast<const float4*>(Bb + (size_t)code * ED + cbase + cp4);
        }
#pragma unroll
        for (int q = 0; q < 2; ++q) {
            int fid = tid + q * 256;
            int c   = fid >> 5;
            int r4  = (fid & 31) * 4;
            *reinterpret_cast<float4*>(&As[0][c][r4]) = ar[q];
            int code = fid >> 2;
            int cp4  = (fid & 3) * 4;
            Bs[0][cp4 + 0][code] = br[q].x;
            Bs[0][cp4 + 1][code] = br[q].y;
            Bs[0][cp4 + 2][code] = br[q].z;
            Bs[0][cp4 + 3][code] = br[q].w;
        }
    }
    __syncthreads();

    // ---- main loop over C in 16 stages of BK=16 (ascending c: matches a
    //      sequential fp32 FFMA accumulation order) ----
    for (int s = 0; s < ED / BK; ++s) {
        const int buf = s & 1;
        if (s < ED / BK - 1) {
            const int cbase = (s + 1) * BK;
#pragma unroll
            for (int q = 0; q < 2; ++q) {
                int fid = tid + q * 256;
                int c   = fid >> 5;
                int r4  = (fid & 31) * 4;
                ar[q] = *reinterpret_cast<const float4*>(Ab + (size_t)(cbase + c) * 1024 + r4);
                int code = fid >> 2;
                int cp4  = (fid & 3) * 4;
                br[q] = *reinterpret_cast<const float4*>(Bb + (size_t)code * ED + cbase + cp4);
            }
        }
#pragma unroll
        for (int cc = 0; cc < BK; ++cc) {
            float a[8], bb[8];
            *reinterpret_cast<float4*>(&a[0]) = *reinterpret_cast<const float4*>(&As[buf][cc][ty * 8]);
            *reinterpret_cast<float4*>(&a[4]) = *reinterpret_cast<const float4*>(&As[buf][cc][ty * 8 + 4]);
            *reinterpret_cast<float4*>(&bb[0]) = *reinterpret_cast<const float4*>(&Bs[buf][cc][tx * 8]);
            *reinterpret_cast<float4*>(&bb[4]) = *reinterpret_cast<const float4*>(&Bs[buf][cc][tx * 8 + 4]);
#pragma unroll
            for (int i = 0; i < 8; ++i)
#pragma unroll
                for (int j = 0; j < 8; ++j)
                    acc[i][j] = fmaf(a[i], bb[j], acc[i][j]);
        }
        if (s < ED / BK - 1) {
            __syncthreads();
            const int nb = (s + 1) & 1;
#pragma unroll
            for (int q = 0; q < 2; ++q) {
                int fid = tid + q * 256;
                int c   = fid >> 5;
                int r4  = (fid & 31) * 4;
                *reinterpret_cast<float4*>(&As[nb][c][r4]) = ar[q];
                int code = fid >> 2;
                int cp4  = (fid & 3) * 4;
                Bs[nb][cp4 + 0][code] = br[q].x;
                Bs[nb][cp4 + 1][code] = br[q].y;
                Bs[nb][cp4 + 2][code] = br[q].z;
                Bs[nb][cp4 + 3][code] = br[q].w;
            }
            __syncthreads();
        }
    }

    // ---- epilogue: replicate reference rounding exactly:
    //      d = fl( fl(z2 + e2) - 2*ez )   (2*ez exact), argmin ties -> lowest idx
    float bd[8];
    int   bi[8];
#pragma unroll
    for (int i = 0; i < 8; ++i) { bd[i] = CUDART_INF_F; bi[i] = 0; }

#pragma unroll
    for (int i = 0; i < 8; ++i) {
        const float z2v = z2s[ty * 8 + i];
#pragma unroll
        for (int j = 0; j < 8; ++j) {        // ascending code index
            float d = __fsub_rn(__fadd_rn(z2v, e2s[tx * 8 + j]), 2.0f * acc[i][j]);
            if (d < bd[i]) { bd[i] = d; bi[i] = col0 + tx * 8 + j; }
        }
    }

    // reduce across the 16 tx threads of each ty row-group (two groups/warp)
#pragma unroll
    for (int i = 0; i < 8; ++i) {
        float d  = bd[i];
        int   ix = bi[i];
#pragma unroll
        for (int off = 8; off; off >>= 1) {
            float d2  = __shfl_down_sync(0xffffffffu, d,  off);
            int   ix2 = __shfl_down_sync(0xffffffffu, ix, off);
            if (d2 < d || (d2 == d && ix2 < ix)) { d = d2; ix = ix2; }
        }
        if (tx == 0) {
            g_bestD[ktile][row0 + ty * 8 + i] = d;
            g_bestI[ktile][row0 + ty * 8 + i] = ix;
        }
    }
}

// ---------------------------------------------------------------
// combine 64 per-ktile partials per row (ascending ktile => strict <
// preserves lowest-index tie-break); emit indices (as float) to out.
// ---------------------------------------------------------------
__global__ void k_combine(float* __restrict__ out) {
    int n = blockIdx.x * blockDim.x + threadIdx.x;
    if (n >= NROWS) return;
    float bd = CUDART_INF_F;
    int   bi = 0;
#pragma unroll 8
    for (int t = 0; t < KTILES; ++t) {
        float d = g_bestD[t][n];
        int   i = g_bestI[t][n];
        if (d < bd) { bd = d; bi = i; }
    }
    g_eidx[n] = bi;
    out[OUT_ZQ + 1 + n] = (float)bi;
}

// ---------------------------------------------------------------
// scrambled gather (faithful to the reference's mislabeled reshape),
// straight-through output fl(zp + fl(zq - zp)), per-block loss partials.
// out[b2][h2][w2][c2] uses codebook[E[b2*1024+w2*32+(c2>>3)]][(c2&7)*32+h2]
// ---------------------------------------------------------------
__global__ void k_gather(const float* __restrict__ z, const float* __restrict__ cb,
                         float* __restrict__ out) {
    __shared__ double red[256];
    const int tid = threadIdx.x;
    const int o = blockIdx.x * 256 + tid;   // < OUT_ZQ

    const int c2 = o & 255;
    const int w2 = (o >> 8) & 31;
    const int h2 = (o >> 13) & 31;
    const int b2 = o >> 18;

    const int n = b2 * 1024 + w2 * 32 + (c2 >> 3);
    const int c = ((c2 & 7) << 5) + h2;

    const float zq = cb[(size_t)g_eidx[n] * ED + c];
    const float zp = z[((((size_t)b2 * ED + c2) * 32 + h2) * 32) + w2];

    // straight-through exactly as reference: zp + (zq - zp) in fp32
    out[o] = __fadd_rn(zp, __fsub_rn(zq, zp));

    const float diff = __fsub_rn(zp, zq);
    red[tid] = (double)(__fmul_rn(diff, diff));
    __syncthreads();
#pragma unroll
    for (int s = 128; s; s >>= 1) {
        if (tid < s) red[tid] += red[tid + s];
        __syncthreads();
    }
    if (tid == 0) g_losspart[blockIdx.x] = red[0];
}

// ---------------------------------------------------------------
// deterministic final loss reduction: loss = 1.25 * mean(diff^2)
// ---------------------------------------------------------------
__global__ void k_loss(float* __restrict__ out) {
    __shared__ double red[256];
    const int tid = threadIdx.x;
    double s = 0.0;
    for (int i = tid; i < 16384; i += 256) s += g_losspart[i];
    red[tid] = s;
    __syncthreads();
#pragma unroll
    for (int st = 128; st; st >>= 1) {
        if (tid < st) red[tid] += red[tid + st];
        __syncthreads();
    }
    if (tid == 0) {
        double L = red[0] / (double)OUT_ZQ;
        out[OUT_ZQ] = (float)(1.25 * L);
    }
}

// ---------------------------------------------------------------
extern "C" void kernel_launch(void* const* d_in, const int* in_sizes, int n_in,
                              void* d_out, int out_size) {
    const float* z  = (const float*)d_in[0];   // [16, 256, 32, 32]
    const float* cb = (const float*)d_in[1];   // [8192, 256]
    float* out = (float*)d_out;

    k_z2<<<NROWS / 256, 256>>>(z);
    k_e2<<<NE / 8, 256>>>(cb);

    dim3 grid(KTILES, MTILES);
    k_argmin<<<grid, 256>>>(z, cb);

    k_combine<<<NROWS / 256, 256>>>(out);
    k_gather<<<OUT_ZQ / 256, 256>>>(z, cb, out);
    k_loss<<<1, 256>>>(out);
}

// round 4
// speedup vs baseline: 1.0322x; 1.0322x over previous
#include <cuda_runtime.h>
#include <math_constants.h>

// Problem constants
#define NE     8192     // num codebook entries
#define ED     256      // embedding dim
#define NROWS  16384    // 16*32*32 flattened vectors
#define OUT_ZQ 4194304  // 16*32*32*256 elements of z_q_st
// out layout: [0, OUT_ZQ) = z_q_st, [OUT_ZQ] = loss, [OUT_ZQ+1, +NROWS) = indices

#define KTILES 64       // 8192 / 128
#define MTILES 128      // 16384 / 128

typedef unsigned long long u64;

// ---- scratch (static device globals; no allocation allowed) ----
__device__ float  g_z2[NROWS];
__device__ float  g_e2[NE];
__device__ u64    g_best[NROWS][KTILES];   // packed (monotone_dist_bits<<32)|idx
__device__ int    g_eidx[NROWS];
__device__ double g_losspart[16384];

// ---- packed f32x2 helpers (Blackwell FFMA2 — ptxas won't emit from C++) ----
__device__ __forceinline__ u64 pack_dup(float x) {
    u64 r; asm("mov.b64 %0, {%1, %1};" : "=l"(r) : "f"(x)); return r;
}
__device__ __forceinline__ void fma2(u64& d, u64 a, u64 b) {
    // d.lo = fma.rn(a.lo, b.lo, d.lo) ; d.hi = fma.rn(a.hi, b.hi, d.hi)
    asm("fma.rn.f32x2 %0, %1, %2, %0;" : "+l"(d) : "l"(a), "l"(b));
}
__device__ __forceinline__ float2 unpack2(u64 v) {
    float2 f; asm("mov.b64 {%0, %1}, %2;" : "=f"(f.x), "=f"(f.y) : "l"(v)); return f;
}
// monotone uint mapping of float (total order, works for any sign)
__device__ __forceinline__ unsigned fkey(float d) {
    unsigned ub = __float_as_uint(d);
    return (ub & 0x80000000u) ? ~ub : (ub | 0x80000000u);
}

// ---------------------------------------------------------------
// z2[n] = sum_c z[b][c][h][w]^2 ; n = b*1024 + h*32 + w
// ---------------------------------------------------------------
__global__ void k_z2(const float* __restrict__ z) {
    int n = blockIdx.x * blockDim.x + threadIdx.x;
    if (n >= NROWS) return;
    int b  = n >> 10;
    int hw = n & 1023;
    const float* p = z + (size_t)b * (ED * 1024) + hw;
    float s = 0.0f;
#pragma unroll 8
    for (int c = 0; c < ED; ++c) {
        float v = p[c * 1024];
        s = fmaf(v, v, s);
    }
    g_z2[n] = s;
}

// ---------------------------------------------------------------
// e2[k] = sum_c codebook[k][c]^2  (warp per code)
// ---------------------------------------------------------------
__global__ void k_e2(const float* __restrict__ cb) {
    int code = blockIdx.x * (blockDim.x >> 5) + (threadIdx.x >> 5);
    int lane = threadIdx.x & 31;
    if (code >= NE) return;
    const float* r = cb + (size_t)code * ED;
    float s = 0.0f;
#pragma unroll
    for (int i = lane; i < ED; i += 32) {
        float v = r[i];
        s = fmaf(v, v, s);
    }
#pragma unroll
    for (int o = 16; o; o >>= 1) s += __shfl_xor_sync(0xffffffffu, s, o);
    if (lane == 0) g_e2[code] = s;
}

// ---------------------------------------------------------------
// Main: per (mtile, ktile) block: 128 rows x 128 codes, full C=256
// dot via packed f32x2 FMA, then quantized-distance argmin partial.
// BM=BN=128, BK=16, 256 threads, 8x8 per thread, smem double buffer.
// ---------------------------------------------------------------
#define BM 128
#define BN 128
#define BK 16

__global__ __launch_bounds__(256, 2)
void k_argmin(const float* __restrict__ z, const float* __restrict__ cb) {
    const int ktile = blockIdx.x;   // 0..63
    const int mtile = blockIdx.y;   // 0..127

    __shared__ __align__(16) float As[2][BK][BM];
    __shared__ __align__(16) float Bs[2][BK][BN];
    __shared__ float z2s[BM];
    __shared__ float e2s[BN];

    const int tid = threadIdx.x;
    const int tx  = tid & 15;
    const int ty  = tid >> 4;

    const int row0 = mtile * BM;
    const int col0 = ktile * BN;

    // A(r,c) = z[b][c][hw0+r] ; all 128 rows share b since 128 | 1024
    const int b   = row0 >> 10;
    const int hw0 = row0 & 1023;
    const float* Ab = z  + (size_t)b    * (ED * 1024) + hw0;
    const float* Bb = cb + (size_t)col0 * ED;

    if (tid < BM) z2s[tid] = g_z2[row0 + tid];
    else          e2s[tid - BM] = g_e2[col0 + (tid - BM)];

    // 8 rows x 4 col-pairs of packed accumulators; 0ull == {+0.f, +0.f}
    u64 acc2[8][4];
#pragma unroll
    for (int i = 0; i < 8; ++i)
#pragma unroll
        for (int j = 0; j < 4; ++j) acc2[i][j] = 0ull;

    float4 ar[2], br[2];

    // ---- stage-0 loads ----
    {
#pragma unroll
        for (int q = 0; q < 2; ++q) {
            int fid = tid + q * 256;          // 0..511
            int c   = fid >> 5;               // 0..15
            int r4  = (fid & 31) * 4;         // 0..124
            ar[q] = *reinterpret_cast<const float4*>(Ab + (size_t)c * 1024 + r4);
            int code = fid >> 2;              // 0..127
            int cp4  = (fid & 3) * 4;         // 0,4,8,12
            br[q] = *reinterpret_cast<const float4*>(Bb + (size_t)code * ED + cp4);
        }
#pragma unroll
        for (int q = 0; q < 2; ++q) {
            int fid = tid + q * 256;
            int c   = fid >> 5;
            int r4  = (fid & 31) * 4;
            *reinterpret_cast<float4*>(&As[0][c][r4]) = ar[q];
            int code = fid >> 2;
            int cp4  = (fid & 3) * 4;
            Bs[0][cp4 + 0][code] = br[q].x;
            Bs[0][cp4 + 1][code] = br[q].y;
            Bs[0][cp4 + 2][code] = br[q].z;
            Bs[0][cp4 + 3][code] = br[q].w;
        }
    }
    __syncthreads();

    // ---- main loop over C: 16 stages of BK=16, ascending c (sequential
    //      per-accumulator fp32 fma chain — bitwise identical to scalar) ----
    for (int s = 0; s < ED / BK; ++s) {
        const int buf = s & 1;
        if (s < ED / BK - 1) {
            const int cbase = (s + 1) * BK;
#pragma unroll
            for (int q = 0; q < 2; ++q) {
                int fid = tid + q * 256;
                int c   = fid >> 5;
                int r4  = (fid & 31) * 4;
                ar[q] = *reinterpret_cast<const float4*>(Ab + (size_t)(cbase + c) * 1024 + r4);
                int code = fid >> 2;
                int cp4  = (fid & 3) * 4;
                br[q] = *reinterpret_cast<const float4*>(Bb + (size_t)code * ED + cbase + cp4);
            }
        }
#pragma unroll
        for (int cc = 0; cc < BK; ++cc) {
            float a[8];
            *reinterpret_cast<float4*>(&a[0]) = *reinterpret_cast<const float4*>(&As[buf][cc][ty * 8]);
            *reinterpret_cast<float4*>(&a[4]) = *reinterpret_cast<const float4*>(&As[buf][cc][ty * 8 + 4]);
            // 8 consecutive B columns as 4 packed pairs (low word = even col)
            ulonglong2 bp0 = *reinterpret_cast<const ulonglong2*>(&Bs[buf][cc][tx * 8]);
            ulonglong2 bp1 = *reinterpret_cast<const ulonglong2*>(&Bs[buf][cc][tx * 8 + 4]);
            u64 bq[4] = {bp0.x, bp0.y, bp1.x, bp1.y};
#pragma unroll
            for (int i = 0; i < 8; ++i) {
                u64 ad = pack_dup(a[i]);
#pragma unroll
                for (int j = 0; j < 4; ++j) fma2(acc2[i][j], ad, bq[j]);
            }
        }
        if (s < ED / BK - 1) {
            __syncthreads();
            const int nb = (s + 1) & 1;
#pragma unroll
            for (int q = 0; q < 2; ++q) {
                int fid = tid + q * 256;
                int c   = fid >> 5;
                int r4  = (fid & 31) * 4;
                *reinterpret_cast<float4*>(&As[nb][c][r4]) = ar[q];
                int code = fid >> 2;
                int cp4  = (fid & 3) * 4;
                Bs[nb][cp4 + 0][code] = br[q].x;
                Bs[nb][cp4 + 1][code] = br[q].y;
                Bs[nb][cp4 + 2][code] = br[q].z;
                Bs[nb][cp4 + 3][code] = br[q].w;
            }
            __syncthreads();
        }
    }

    // ---- epilogue: d = fl( fl(z2 + e2) - 2*ez ), packed argmin key:
    //      (monotone_dist_bits << 32) | idx  — strict < keeps lowest idx on tie
    u64 bkey[8];
#pragma unroll
    for (int i = 0; i < 8; ++i) bkey[i] = ~0ull;

#pragma unroll
    for (int i = 0; i < 8; ++i) {
        const float z2v = z2s[ty * 8 + i];
#pragma unroll
        for (int j = 0; j < 4; ++j) {        // ascending code index
            float2 p = unpack2(acc2[i][j]);
            int c0 = tx * 8 + 2 * j;
            float d0 = __fsub_rn(__fadd_rn(z2v, e2s[c0]),     2.0f * p.x);
            float d1 = __fsub_rn(__fadd_rn(z2v, e2s[c0 + 1]), 2.0f * p.y);
            u64 k0 = ((u64)fkey(d0) << 32) | (unsigned)(col0 + c0);
            u64 k1 = ((u64)fkey(d1) << 32) | (unsigned)(col0 + c0 + 1);
            if (k0 < bkey[i]) bkey[i] = k0;
            if (k1 < bkey[i]) bkey[i] = k1;
        }
    }

    // reduce across the 16 tx threads of each ty row-group
#pragma unroll
    for (int i = 0; i < 8; ++i) {
        u64 k = bkey[i];
#pragma unroll
        for (int off = 8; off; off >>= 1) {
            u64 k2 = __shfl_down_sync(0xffffffffu, k, off);
            if (k2 < k) k = k2;
        }
        if (tx == 0) g_best[row0 + ty * 8 + i][ktile] = k;
    }
}

// ---------------------------------------------------------------
// combine: warp per row, coalesced read of 64 packed keys, min-reduce.
// ---------------------------------------------------------------
__global__ void k_combine(float* __restrict__ out) {
    int warp = (blockIdx.x * blockDim.x + threadIdx.x) >> 5;
    int lane = threadIdx.x & 31;
    if (warp >= NROWS) return;
    const u64* row = g_best[warp];
    u64 k0 = row[lane];
    u64 k1 = row[lane + 32];
    u64 k  = (k1 < k0) ? k1 : k0;
#pragma unroll
    for (int off = 16; off; off >>= 1) {
        u64 k2 = __shfl_down_sync(0xffffffffu, k, off);
        if (k2 < k) k = k2;
    }
    if (lane == 0) {
        int bi = (int)(unsigned)(k & 0xffffffffu);
        g_eidx[warp] = bi;
        out[OUT_ZQ + 1 + warp] = (float)bi;
    }
}

// ---------------------------------------------------------------
// scrambled gather (faithful to the reference's mislabeled reshape),
// straight-through output fl(zp + fl(zq - zp)), per-block loss partials.
// ---------------------------------------------------------------
__global__ void k_gather(const float* __restrict__ z, const float* __restrict__ cb,
                         float* __restrict__ out) {
    __shared__ double red[256];
    const int tid = threadIdx.x;
    const int o = blockIdx.x * 256 + tid;   // < OUT_ZQ

    const int c2 = o & 255;
    const int w2 = (o >> 8) & 31;
    const int h2 = (o >> 13) & 31;
    const int b2 = o >> 18;

    const int n = b2 * 1024 + w2 * 32 + (c2 >> 3);
    const int c = ((c2 & 7) << 5) + h2;

    const float zq = cb[(size_t)g_eidx[n] * ED + c];
    const float zp = z[((((size_t)b2 * ED + c2) * 32 + h2) * 32) + w2];

    // straight-through exactly as reference: zp + (zq - zp) in fp32
    out[o] = __fadd_rn(zp, __fsub_rn(zq, zp));

    const float diff = __fsub_rn(zp, zq);
    red[tid] = (double)(__fmul_rn(diff, diff));
    __syncthreads();
#pragma unroll
    for (int s = 128; s; s >>= 1) {
        if (tid < s) red[tid] += red[tid + s];
        __syncthreads();
    }
    if (tid == 0) g_losspart[blockIdx.x] = red[0];
}

// ---------------------------------------------------------------
// deterministic final loss reduction: loss = 1.25 * mean(diff^2)
// ---------------------------------------------------------------
__global__ void k_loss(float* __restrict__ out) {
    __shared__ double red[256];
    const int tid = threadIdx.x;
    double s = 0.0;
    for (int i = tid; i < 16384; i += 256) s += g_losspart[i];
    red[tid] = s;
    __syncthreads();
#pragma unroll
    for (int st = 128; st; st >>= 1) {
        if (tid < st) red[tid] += red[tid + st];
        __syncthreads();
    }
    if (tid == 0) {
        double L = red[0] / (double)OUT_ZQ;
        out[OUT_ZQ] = (float)(1.25 * L);
    }
}

// ---------------------------------------------------------------
extern "C" void kernel_launch(void* const* d_in, const int* in_sizes, int n_in,
                              void* d_out, int out_size) {
    const float* z  = (const float*)d_in[0];   // [16, 256, 32, 32]
    const float* cb = (const float*)d_in[1];   // [8192, 256]
    float* out = (float*)d_out;

    k_z2<<<NROWS / 256, 256>>>(z);
    k_e2<<<NE / 8, 256>>>(cb);

    dim3 grid(KTILES, MTILES);
    k_argmin<<<grid, 256>>>(z, cb);

    k_combine<<<NROWS * 32 / 256, 256>>>(out);
    k_gather<<<OUT_ZQ / 256, 256>>>(z, cb, out);
    k_loss<<<1, 256>>>(out);
}

// round 10
// speedup vs baseline: 2.0193x; 1.9563x over previous
#include <cuda_runtime.h>
#include <cuda_bf16.h>
#include <math_constants.h>
#include <cstdint>

// Problem constants
#define NE     8192     // num codebook entries
#define ED     256      // embedding dim
#define NROWS  16384    // 16*32*32 flattened vectors
#define OUT_ZQ 4194304  // 16*32*32*256 elements of z_q_st
// out layout: [0, OUT_ZQ) = z_q_st, [OUT_ZQ] = loss, [OUT_ZQ+1, +NROWS) = indices

#define NGROUPS 64      // 8192 / 128 candidate groups (one group per CTA col-tile)
#define MTILES  128     // 16384 / 128

typedef unsigned long long u64;

// ---- scratch (static device globals; no allocation allowed) ----
__device__ float  g_z2[NROWS];
__device__ float  g_e2[NE];
__device__ int    g_e2max_i;
__device__ __align__(16) __nv_bfloat16 g_zbf[NROWS * ED];   // [n][c] bf16
__device__ __align__(16) float         g_zt [NROWS * ED];   // [n][c] fp32 (for exact rescore)
__device__ __align__(16) __nv_bfloat16 g_cbbf[NE * ED];     // [k][c] bf16
__device__ u64    g_best1[NROWS][NGROUPS];
__device__ u64    g_best2[NROWS][NGROUPS];
__device__ int    g_eidx[NROWS];
__device__ double g_losspart[16384];

// =================== helpers ===================
__device__ __forceinline__ uint32_t smem_u32(const void* p) {
    uint32_t a;
    asm("{ .reg .u64 t; cvta.to.shared.u64 t, %1; cvt.u32.u64 %0, t; }" : "=r"(a) : "l"(p));
    return a;
}
__device__ __forceinline__ void cp_async16(uint32_t dst, const void* src) {
    asm volatile("cp.async.cg.shared.global [%0], [%1], 16;" :: "r"(dst), "l"(src) : "memory");
}
__device__ __forceinline__ void ldsm_x4(uint32_t* r, uint32_t addr) {
    asm volatile("ldmatrix.sync.aligned.m8n8.x4.shared.b16 {%0,%1,%2,%3}, [%4];"
                 : "=r"(r[0]), "=r"(r[1]), "=r"(r[2]), "=r"(r[3]) : "r"(addr));
}
__device__ __forceinline__ void mma16816(float* c, const uint32_t* a, uint32_t b0, uint32_t b1) {
    asm volatile("mma.sync.aligned.m16n8k16.row.col.f32.bf16.bf16.f32 "
                 "{%0,%1,%2,%3}, {%4,%5,%6,%7}, {%8,%9}, {%0,%1,%2,%3};"
                 : "+f"(c[0]), "+f"(c[1]), "+f"(c[2]), "+f"(c[3])
                 : "r"(a[0]), "r"(a[1]), "r"(a[2]), "r"(a[3]), "r"(b0), "r"(b1));
}
// monotone key helpers
__device__ __forceinline__ unsigned fkey(float d) {
    unsigned ub = __float_as_uint(d);
    return (ub & 0x80000000u) ? ~ub : (ub | 0x80000000u);
}
__device__ __forceinline__ float unfkey(unsigned u) {
    unsigned ub = (u & 0x80000000u) ? (u ^ 0x80000000u) : ~u;
    return __uint_as_float(ub);
}
__device__ __forceinline__ void upd2(u64 key, u64& k1, u64& k2) {
    if (key < k1) { k2 = k1; k1 = key; }
    else if (key < k2) { k2 = key; }
}

// =================== prep kernels ===================

__global__ void k_z2(const float* __restrict__ z) {
    int n = blockIdx.x * blockDim.x + threadIdx.x;
    if (n == 0) g_e2max_i = 0;
    if (n >= NROWS) return;
    int b  = n >> 10;
    int hw = n & 1023;
    const float* p = z + (size_t)b * (ED * 1024) + hw;
    float s = 0.0f;
#pragma unroll 8
    for (int c = 0; c < ED; ++c) { float v = p[c * 1024]; s = fmaf(v, v, s); }
    g_z2[n] = s;
}

__global__ void k_e2(const float* __restrict__ cb) {
    int code = blockIdx.x * (blockDim.x >> 5) + (threadIdx.x >> 5);
    int lane = threadIdx.x & 31;
    if (code >= NE) return;
    const float* r = cb + (size_t)code * ED;
    float s = 0.0f;
#pragma unroll
    for (int i = lane; i < ED; i += 32) { float v = r[i]; s = fmaf(v, v, s); }
#pragma unroll
    for (int o = 16; o; o >>= 1) s += __shfl_xor_sync(0xffffffffu, s, o);
    if (lane == 0) {
        g_e2[code] = s;
        atomicMax(&g_e2max_i, __float_as_int(s));   // positive floats: int order ok
    }
}

// transpose z [b][c][h][w] -> [n][c] as bf16 (GEMM) and fp32 (exact rescore)
__global__ void k_trz(const float* __restrict__ z) {
    __shared__ float tile[32][33];
    int n0 = blockIdx.x * 32;
    int c0 = blockIdx.y * 32;
    int b = n0 >> 10, hw0 = n0 & 1023;
#pragma unroll
    for (int i = 0; i < 4; ++i) {
        int cc = threadIdx.y + i * 8;
        tile[threadIdx.x][cc] = z[(size_t)b * (ED * 1024) + (size_t)(c0 + cc) * 1024 + hw0 + threadIdx.x];
    }
    __syncthreads();
#pragma unroll
    for (int i = 0; i < 4; ++i) {
        int nn = threadIdx.y + i * 8;
        float v = tile[nn][threadIdx.x];
        g_zbf[(size_t)(n0 + nn) * ED + c0 + threadIdx.x] = __float2bfloat16_rn(v);
        g_zt [(size_t)(n0 + nn) * ED + c0 + threadIdx.x] = v;
    }
}

__global__ void k_cbconv(const float* __restrict__ cb) {
    int i = blockIdx.x * blockDim.x + threadIdx.x;
    if (i < NE * ED) g_cbbf[i] = __float2bfloat16_rn(cb[i]);
}

// =================== main HMMA kernel ===================
// CTA: 128 rows x 128 codes (= one candidate group), K=256 as 4 stages of 64.
// 8 warps = 4(M) x 2(N); warp tile 32x64 = 2 x 8 m16n8k16 tiles.
// smem stage: A 128x128B + B 128x128B, SW128-pattern swizzle, double buffered.
// dyn smem: [0,64K) stages | 64K e2[128] | 64K+512 sk1[2][128] | +2048 sk2[2][128]

#define SMS_E2  65536
#define SMS_K1  (65536 + 512)
#define SMS_K2  (SMS_K1 + 2048)
#define SMS_TOT (SMS_K2 + 2048)

__global__ __launch_bounds__(256) void k_mma() {
    extern __shared__ char smem[];
    const uint32_t sb = smem_u32(smem);
    const int tid = threadIdx.x;
    const int wid = tid >> 5;
    const int lid = tid & 31;

    const int group = blockIdx.x;          // 0..63
    const int mtile = blockIdx.y;          // 0..127
    const int row0 = mtile * 128;
    const int col0 = group * 128;

    const int wm = wid >> 1;               // 0..3 (M)
    const int wn = wid & 1;                // 0..1 (N)

    float* e2s = (float*)(smem + SMS_E2);
    if (tid < 128) e2s[tid] = g_e2[col0 + tid];

    // per-lane ldmatrix address components
    const int hlA = lid >> 4;                                  // 0/1 (k 16B-unit)
    const uint32_t aRowOff0 = (uint32_t)(wm * 32 + (lid & 15)) * 128;
    const int hlB = (lid >> 3) & 1;
    const int nlB = (lid & 7) + ((lid >> 4) << 3);             // 0..15 within pair

    float acc[2][8][4];
#pragma unroll
    for (int i = 0; i < 2; ++i)
#pragma unroll
        for (int j = 0; j < 8; ++j)
#pragma unroll
            for (int v = 0; v < 4; ++v) acc[i][j][v] = 0.0f;

    // ---- stage prefetch: stage s -> buffer buf ----
    auto prefetch = [&](int s, int buf) {
#pragma unroll
        for (int i = 0; i < 4; ++i) {
            int u = tid + i * 256;          // 0..1023
            int r = u >> 3, h = u & 7;
            uint32_t dst = sb + (uint32_t)buf * 32768 + (uint32_t)(r * 128 + ((h ^ (r & 7)) * 16));
            cp_async16(dst, (const char*)g_zbf + ((size_t)(row0 + r) * ED + s * 64 + h * 8) * 2);
        }
#pragma unroll
        for (int i = 0; i < 4; ++i) {
            int u = tid + i * 256;
            int r = u >> 3, h = u & 7;
            uint32_t dst = sb + (uint32_t)buf * 32768 + 16384u + (uint32_t)(r * 128 + ((h ^ (r & 7)) * 16));
            cp_async16(dst, (const char*)g_cbbf + ((size_t)(col0 + r) * ED + s * 64 + h * 8) * 2);
        }
        asm volatile("cp.async.commit_group;" ::: "memory");
    };

    auto compute = [&](int buf) {
        const uint32_t Ab = sb + (uint32_t)buf * 32768;
        const uint32_t Bb = Ab + 16384u;
#pragma unroll
        for (int kk = 0; kk < 4; ++kk) {
            uint32_t a[2][4];
#pragma unroll
            for (int tm = 0; tm < 2; ++tm) {
                uint32_t addr = Ab + aRowOff0 + (uint32_t)(tm * 16 * 128)
                              + (uint32_t)(((kk * 2 + hlA) ^ (lid & 7)) * 16);
                ldsm_x4(a[tm], addr);
            }
            uint32_t b[4][4];
#pragma unroll
            for (int p = 0; p < 4; ++p) {
                uint32_t addr = Bb + (uint32_t)((wn * 64 + p * 16 + nlB) * 128)
                              + (uint32_t)(((kk * 2 + hlB) ^ (lid & 7)) * 16);
                ldsm_x4(b[p], addr);
            }
#pragma unroll
            for (int tm = 0; tm < 2; ++tm)
#pragma unroll
                for (int p = 0; p < 4; ++p) {
                    mma16816(acc[tm][2 * p],     a[tm], b[p][0], b[p][1]);
                    mma16816(acc[tm][2 * p + 1], a[tm], b[p][2], b[p][3]);
                }
        }
    };

    prefetch(0, 0);
    prefetch(1, 1);
#pragma unroll
    for (int s = 0; s < 4; ++s) {
        if (s < 3) { asm volatile("cp.async.wait_group 1;" ::: "memory"); }
        else       { asm volatile("cp.async.wait_group 0;" ::: "memory"); }
        __syncthreads();
        compute(s & 1);
        __syncthreads();
        if (s + 2 < 4) prefetch(s + 2, s & 1);
    }

    // ---- epilogue: d = fl(fl(z2+e2) - 2*ez_bf16); per-row min1/min2 over group ----
    const int g = lid >> 2;
    const int tig = lid & 3;
    u64* sk1 = (u64*)(smem + SMS_K1);   // [2][128]
    u64* sk2 = (u64*)(smem + SMS_K2);

#pragma unroll
    for (int tm = 0; tm < 2; ++tm) {
#pragma unroll
        for (int half = 0; half < 2; ++half) {
            const int r = wm * 32 + tm * 16 + g + half * 8;
            const float z2v = g_z2[row0 + r];
            u64 k1 = ~0ull, k2 = ~0ull;
#pragma unroll
            for (int tn = 0; tn < 8; ++tn) {
#pragma unroll
                for (int v = 0; v < 2; ++v) {
                    int cl = wn * 64 + tn * 8 + 2 * tig + v;
                    float d = __fsub_rn(__fadd_rn(z2v, e2s[cl]),
                                        2.0f * acc[tm][tn][half * 2 + v]);
                    u64 key = ((u64)fkey(d) << 32) | (unsigned)(col0 + cl);
                    upd2(key, k1, k2);
                }
            }
            // quad merge (threads sharing this row: tig 0..3)
#pragma unroll
            for (int off = 1; off <= 2; off <<= 1) {
                u64 o1 = __shfl_xor_sync(0xffffffffu, k1, off);
                u64 o2 = __shfl_xor_sync(0xffffffffu, k2, off);
                upd2(o1, k1, k2);
                upd2(o2, k1, k2);
            }
            if (tig == 0) {
                sk1[wn * 128 + r] = k1;
                sk2[wn * 128 + r] = k2;
            }
        }
    }
    __syncthreads();
    if (tid < 128) {
        u64 k1 = sk1[tid], k2 = sk2[tid];
        upd2(sk1[128 + tid], k1, k2);
        upd2(sk2[128 + tid], k1, k2);
        g_best1[row0 + tid][group] = k1;
        g_best2[row0 + tid][group] = k2;
    }
}

// =================== exact rescore + index emit ===================
__global__ __launch_bounds__(128) void k_exact(const float* __restrict__ cb,
                                               float* __restrict__ out) {
    __shared__ float zrow[ED];
    __shared__ u64 sk1[NGROUPS], sk2[NGROUPS];
    __shared__ unsigned short cand[1024];
    __shared__ int scnt, smode;
    __shared__ u64 sbest;

    const int row = blockIdx.x;
    const int t = threadIdx.x;

    zrow[t]       = g_zt[(size_t)row * ED + t];
    zrow[t + 128] = g_zt[(size_t)row * ED + t + 128];
    if (t < NGROUPS) { sk1[t] = g_best1[row][t]; sk2[t] = g_best2[row][t]; }
    if (t == 0) { scnt = 0; smode = 0; sbest = ~0ull; }
    __syncthreads();

    if (t == 0) {
        u64 gmin = ~0ull;
#pragma unroll 8
        for (int i = 0; i < NGROUPS; ++i) if (sk1[i] < gmin) gmin = sk1[i];
        float dmin = unfkey((unsigned)(gmin >> 32));
        float ax = fabsf(dmin);
        float ulp = (ax > 1e-20f) ? ldexpf(1.0f, ilogbf(ax) - 23) : 1e-20f;
        float e2max = __int_as_float(g_e2max_i);
        float tau = 4.0f * (ulp + 0.0078125f * sqrtf(g_z2[row] * e2max));
        float thr = dmin + tau;
        int cnt = 0, mode = 0;
        for (int gi = 0; gi < NGROUPS; ++gi) {
            float d1 = unfkey((unsigned)(sk1[gi] >> 32));
            if (d1 <= thr) {
                float d2 = unfkey((unsigned)(sk2[gi] >> 32));
                if (d2 <= thr) {
                    if (cnt + 128 <= 1024) {
                        for (int j = 0; j < 128; ++j) cand[cnt++] = (unsigned short)(gi * 128 + j);
                    } else mode = 1;
                } else {
                    if (cnt < 1024) cand[cnt++] = (unsigned short)(sk1[gi] & 0xffffu);
                    else mode = 1;
                }
            }
        }
        scnt = cnt; smode = mode;
    }
    __syncthreads();

    const float z2v = g_z2[row];
    if (smode == 0) {
        for (int i = t; i < scnt; i += 128) {
            int k = cand[i];
            const float* e = cb + (size_t)k * ED;
            float acc = 0.0f;
#pragma unroll 8
            for (int c = 0; c < ED; ++c) acc = fmaf(zrow[c], e[c], acc);
            float d = __fsub_rn(__fadd_rn(z2v, g_e2[k]), 2.0f * acc);
            u64 key = ((u64)fkey(d) << 32) | (unsigned)k;
            atomicMin(&sbest, key);
        }
    } else {
        for (int k = t; k < NE; k += 128) {
            const float* e = cb + (size_t)k * ED;
            float acc = 0.0f;
#pragma unroll 8
            for (int c = 0; c < ED; ++c) acc = fmaf(zrow[c], e[c], acc);
            float d = __fsub_rn(__fadd_rn(z2v, g_e2[k]), 2.0f * acc);
            u64 key = ((u64)fkey(d) << 32) | (unsigned)k;
            atomicMin(&sbest, key);
        }
    }
    __syncthreads();
    if (t == 0) {
        int bi = (int)(unsigned)(sbest & 0xffffffffu);
        g_eidx[row] = bi;
        out[OUT_ZQ + 1 + row] = (float)bi;
    }
}

// =================== gather + loss (bitwise-validated in R3/R4) ===================
__global__ void k_gather(const float* __restrict__ z, const float* __restrict__ cb,
                         float* __restrict__ out) {
    __shared__ double red[256];
    const int tid = threadIdx.x;
    const int o = blockIdx.x * 256 + tid;

    const int c2 = o & 255;
    const int w2 = (o >> 8) & 31;
    const int h2 = (o >> 13) & 31;
    const int b2 = o >> 18;

    const int n = b2 * 1024 + w2 * 32 + (c2 >> 3);
    const int c = ((c2 & 7) << 5) + h2;

    const float zq = cb[(size_t)g_eidx[n] * ED + c];
    const float zp = z[((((size_t)b2 * ED + c2) * 32 + h2) * 32) + w2];

    out[o] = __fadd_rn(zp, __fsub_rn(zq, zp));

    const float diff = __fsub_rn(zp, zq);
    red[tid] = (double)(__fmul_rn(diff, diff));
    __syncthreads();
#pragma unroll
    for (int s = 128; s; s >>= 1) {
        if (tid < s) red[tid] += red[tid + s];
        __syncthreads();
    }
    if (tid == 0) g_losspart[blockIdx.x] = red[0];
}

__global__ void k_loss(float* __restrict__ out) {
    __shared__ double red[256];
    const int tid = threadIdx.x;
    double s = 0.0;
    for (int i = tid; i < 16384; i += 256) s += g_losspart[i];
    red[tid] = s;
    __syncthreads();
#pragma unroll
    for (int st = 128; st; st >>= 1) {
        if (tid < st) red[tid] += red[tid + st];
        __syncthreads();
    }
    if (tid == 0) {
        double L = red[0] / (double)OUT_ZQ;
        out[OUT_ZQ] = (float)(1.25 * L);
    }
}

// ---------------------------------------------------------------
extern "C" void kernel_launch(void* const* d_in, const int* in_sizes, int n_in,
                              void* d_out, int out_size) {
    const float* z  = (const float*)d_in[0];   // [16, 256, 32, 32]
    const float* cb = (const float*)d_in[1];   // [8192, 256]
    float* out = (float*)d_out;

    cudaFuncSetAttribute(k_mma, cudaFuncAttributeMaxDynamicSharedMemorySize, SMS_TOT);

    k_z2<<<NROWS / 256, 256>>>(z);
    k_e2<<<NE / 8, 256>>>(cb);
    k_trz<<<dim3(NROWS / 32, ED / 32), dim3(32, 8)>>>(z);
    k_cbconv<<<(NE * ED) / 256, 256>>>(cb);

    k_mma<<<dim3(NGROUPS, MTILES), 256, SMS_TOT>>>();

    k_exact<<<NROWS, 128>>>(cb, out);
    k_gather<<<OUT_ZQ / 256, 256>>>(z, cb, out);
    k_loss<<<1, 256>>>(out);
}